// round 1
// baseline (speedup 1.0000x reference)
#include <cuda_runtime.h>

// ---------------- problem constants ----------------
#define NCLS   19
#define BATCH  8
#define HH     512
#define WW     512
#define HW     (HH*WW)            // 262144
#define NPIX   (BATCH*HW)         // 2097152
#define NLOG   1000
#define DDIM   768

#define TPB    256
#define IPT    16
#define BLK_PIX (TPB*IPT)         // 4096
#define BLKS_PER_B (HW/BLK_PIX)   // 64

// ---------------- scratch (no allocations allowed) ----------------
__device__ float  g_union[BATCH*NCLS];
__device__ float  g_inter[BATCH*NCLS];
__device__ double g_focal;

// ---------------- kernel 0: zero scratch (graph replay safe) ----------------
__global__ void zero_kernel() {
    int t = threadIdx.x;
    if (t < BATCH*NCLS) { g_union[t] = 0.f; g_inter[t] = 0.f; }
    if (t == 0) g_focal = 0.0;
}

// ---------------- kernel 1: fused dice sums + focal over seg tensor ----------------
__global__ __launch_bounds__(TPB)
void seg_kernel(const float* __restrict__ pred, const int* __restrict__ gt) {
    const int b   = blockIdx.y;
    const int tid = threadIdx.x;
    const int base = blockIdx.x * BLK_PIX + tid;

    const float* __restrict__ pb = pred + (size_t)b * NCLS * HW;
    const int*   __restrict__ gb = gt   + (size_t)b * HW;

    // constant-indexed register accumulators (no dynamic indexing -> no spills)
    float un[NCLS], in_[NCLS];
#pragma unroll
    for (int c = 0; c < NCLS; c++) { un[c] = 0.f; in_[c] = 0.f; }
    float fo = 0.f;

#pragma unroll 1
    for (int k = 0; k < IPT; k++) {
        const int pix = base + k * TPB;
        const int g = gb[pix];

        float v[NCLS];
        float m = -1e30f;
        const float* p = pb + pix;
#pragma unroll
        for (int c = 0; c < NCLS; c++) {
            v[c] = p[(size_t)c * HW];          // 19 independent coalesced LDGs (high MLP)
            m = fmaxf(m, v[c]);
        }

        float se = 0.f, vg = 0.f;
#pragma unroll
        for (int c = 0; c < NCLS; c++) {
            se += __expf(v[c] - m);
            float ms = (c == g) ? 1.0f : 0.0f;  // float mask -> FFMA accumulation
            un[c] += v[c] + ms;                 // union = sum(pred) + count(onehot)
            in_[c] = fmaf(ms, v[c], in_[c]);    // inter = pred at gt class
            vg = fmaf(ms, v[c], vg);            // v[g] without dynamic indexing
        }

        const float lpt = vg - m - __logf(se);  // log p_t
        const float pt  = __expf(lpt);
        const float om  = 1.f - pt;
        fo = fmaf(0.25f * om * om, -lpt, fo);   // ALPHA*(1-p)^GAMMA*ce
    }

    // ---- per-block reduction: shfl -> shared -> few global atomics ----
    __shared__ float su[NCLS], si[NCLS], sf[8];
    if (tid < NCLS) { su[tid] = 0.f; si[tid] = 0.f; }
    __syncthreads();

#pragma unroll
    for (int c = 0; c < NCLS; c++) {
        float u = un[c], i = in_[c];
        for (int o = 16; o; o >>= 1) {
            u += __shfl_xor_sync(0xffffffffu, u, o);
            i += __shfl_xor_sync(0xffffffffu, i, o);
        }
        if ((tid & 31) == 0) { atomicAdd(&su[c], u); atomicAdd(&si[c], i); }
    }
    for (int o = 16; o; o >>= 1) fo += __shfl_xor_sync(0xffffffffu, fo, o);
    if ((tid & 31) == 0) sf[tid >> 5] = fo;
    __syncthreads();

    if (tid < NCLS) {
        atomicAdd(&g_union[b * NCLS + tid], su[tid]);
        atomicAdd(&g_inter[b * NCLS + tid], si[tid]);
    }
    if (tid == 0) {
        float s = 0.f;
#pragma unroll
        for (int w = 0; w < 8; w++) s += sf[w];
        atomicAdd(&g_focal, (double)s);
    }
}

// ---------------- block reduce helper (finalize kernel, 256 threads) ----------------
__device__ __forceinline__ float bred256(float v) {
    __shared__ float s[8];
    for (int o = 16; o; o >>= 1) v += __shfl_xor_sync(0xffffffffu, v, o);
    __syncthreads();
    if ((threadIdx.x & 31) == 0) s[threadIdx.x >> 5] = v;
    __syncthreads();
    float r = 0.f;
    if (threadIdx.x == 0) {
#pragma unroll
        for (int w = 0; w < 8; w++) r += s[w];
    }
    return r;  // valid on thread 0
}

// ---------------- kernel 2: CE + modal balance + combine ----------------
__global__ __launch_bounds__(256)
void finalize_kernel(const float* __restrict__ logits, const int* __restrict__ label,
                     const float* __restrict__ vfeat,  const float* __restrict__ tfeat,
                     const float* __restrict__ mmask,  const int* __restrict__ epoch_p,
                     float* __restrict__ out) {
    const int tid = threadIdx.x, wid = tid >> 5, lane = tid & 31;
    __shared__ float s_ce[8], s_invv[8], s_invt[8];

    // --- CE per row (warp per row) + feature norms ---
    {
        const float* row = logits + wid * NLOG;
        float m = -1e30f;
        for (int j = lane; j < NLOG; j += 32) m = fmaxf(m, row[j]);
        for (int o = 16; o; o >>= 1) m = fmaxf(m, __shfl_xor_sync(0xffffffffu, m, o));
        float se = 0.f;
        for (int j = lane; j < NLOG; j += 32) se += __expf(row[j] - m);
        for (int o = 16; o; o >>= 1) se += __shfl_xor_sync(0xffffffffu, se, o);

        const float* vr = vfeat + wid * DDIM;
        const float* tr = tfeat + wid * DDIM;
        float sv = 0.f, st = 0.f;
        for (int j = lane; j < DDIM; j += 32) {
            float a = vr[j]; sv = fmaf(a, a, sv);
            float c = tr[j]; st = fmaf(c, c, st);
        }
        for (int o = 16; o; o >>= 1) {
            sv += __shfl_xor_sync(0xffffffffu, sv, o);
            st += __shfl_xor_sync(0xffffffffu, st, o);
        }
        if (lane == 0) {
            float xl = row[label[wid]];
            s_ce[wid]   = -(xl - m - __logf(se));
            s_invv[wid] = 1.0f / sqrtf(sv);
            s_invt[wid] = 1.0f / sqrtf(st);
        }
    }
    __syncthreads();

    // --- modal balance: per-dimension pass ---
    float a_v2 = 0.f, a_mv = 0.f, a_t2 = 0.f, a_mt = 0.f, a_x = 0.f;
    for (int d = tid; d < DDIM; d += 256) {
        float s1v = 0.f, s2v = 0.f, s1t = 0.f, s2t = 0.f, x = 0.f;
#pragma unroll
        for (int b = 0; b < BATCH; b++) {
            float vn = vfeat[b * DDIM + d] * s_invv[b];
            float tn = tfeat[b * DDIM + d] * s_invt[b];
            s1v += vn; s2v = fmaf(vn, vn, s2v);
            s1t += tn; s2t = fmaf(tn, tn, s2t);
            x = fmaf(vn, tn, x);
        }
        a_v2 += s2v; a_t2 += s2t; a_x += x;
        float mv = s1v * 0.125f, mt = s1t * 0.125f;
        a_mv = fmaf(mv, mv, a_mv);
        a_mt = fmaf(mt, mt, a_mt);
    }
    float r_v2 = bred256(a_v2);
    float r_mv = bred256(a_mv);
    float r_t2 = bred256(a_t2);
    float r_mt = bred256(a_mt);
    float r_x  = bred256(a_x);

    // --- dice finalize ---
    float dl = 0.f;
    if (tid < BATCH * NCLS) {
        float u = g_union[tid], i = g_inter[tid];
        float dice = (2.f * i + 1e-5f) / (u + 1e-5f);
        dl = 1.f - dice;
    }
    float r_dl = bred256(dl);

    if (tid == 0) {
        float ce = 0.f;
#pragma unroll
        for (int b = 0; b < BATCH; b++) ce += s_ce[b];
        ce *= (1.0f / BATCH);

        float v_cons = r_v2 / (float)(BATCH * DDIM) - r_mv / (float)DDIM;
        float t_cons = r_t2 / (float)(BATCH * DDIM) - r_mt / (float)DDIM;
        float cross  = 1.f - r_x / (float)BATCH;

        float m0 = 0.f, m1 = 0.f;
#pragma unroll
        for (int b = 0; b < BATCH; b++) { m0 += mmask[2 * b]; m1 += mmask[2 * b + 1]; }
        m0 *= (1.0f / BATCH); m1 *= (1.0f / BATCH);

        int e = epoch_p[0];
        if (e < 0 || e > 1000000) {           // dtype guard: epoch stored as float32
            e = (int)__int_as_float(e);
        }
        float beta = (float)(0.5 * pow(0.99, (double)e));

        float mb = (1.f - beta) * v_cons * m0 + beta * t_cons * m1 + cross;
        float focal = (float)(g_focal / (double)NPIX);
        float seg = r_dl / (float)(BATCH * NCLS) + focal;

        out[0] = ce + 0.3f * mb + 0.5f * seg;
    }
}

// ---------------- launch ----------------
extern "C" void kernel_launch(void* const* d_in, const int* in_sizes, int n_in,
                              void* d_out, int out_size) {
    const float* logits = (const float*)d_in[0];
    const int*   label  = (const int*)  d_in[1];
    const float* vfeat  = (const float*)d_in[2];
    const float* tfeat  = (const float*)d_in[3];
    const float* mmask  = (const float*)d_in[4];
    const float* segm   = (const float*)d_in[5];
    const int*   seggt  = (const int*)  d_in[6];
    const int*   epoch  = (const int*)  d_in[7];
    float* out = (float*)d_out;

    zero_kernel<<<1, 256>>>();
    seg_kernel<<<dim3(BLKS_PER_B, BATCH), TPB>>>(segm, seggt);
    finalize_kernel<<<1, 256>>>(logits, label, vfeat, tfeat, mmask, epoch, out);
}